// round 17
// baseline (speedup 1.0000x reference)
#include <cuda_runtime.h>
#include <cuda_fp16.h>
#include <mma.h>
#include <cstdint>

using namespace nvcuda;

#define N_NODES 100000
#define NE      1600000
#define D       128
#define NB      ((N_NODES + 255) / 256)

#define SLOTS      64                     // 64 ints = 256B per node, 128B-aligned
#define OVF_CAP    4096                   // overflow entries for deg > SLOTS

#define GEMM_TILES    782                 // 128 rows each
#define GEMM_BLOCKS   296                 // persistent: 2 per SM x 148
#define EDGE_BLOCKS8  782                 // fill: 2048 edges per block (256 thr x 8)

// smem for GEMM: W (64 KB) + C staging (32 KB) = 96 KB
#define SMEM_W_FLOATS (D * D)
#define SMEM_C_FLOATS (8 * 16 * 64)
#define SMEM_GEMM     ((SMEM_W_FLOATS + SMEM_C_FLOATS) * (int)sizeof(float))

// Scratch (__device__ globals; no allocation)
__device__ __align__(16) __half g_Yh[(size_t)N_NODES * D];   // 25.6 MB
__device__ int g_degi[N_NODES];                               // cursor + degree
__device__ int g_adj[(size_t)N_NODES * SLOTS];                // 25.6 MB slot adjacency
__device__ int g_ovf_node[OVF_CAP];
__device__ int g_ovf_nbr[OVF_CAP];
__device__ int g_ovf_cnt;
__device__ int g_is64;

// ---------------------------------------------------------------------------
// probe (thread 0) + zero degrees + zero overflow counter.
// Ring edges are small ints: for int64 the odd 32-bit words of the first 32
// words are all zero; for int32 they are 1,3,5,...
// ---------------------------------------------------------------------------
__global__ void probe_zero_kernel(const int* __restrict__ ei) {
    int i = blockIdx.x * blockDim.x + threadIdx.x;
    if (i == 0) {
        int acc = 0;
#pragma unroll
        for (int k = 1; k < 32; k += 2) acc |= ei[k];
        g_is64 = (acc == 0) ? 1 : 0;
        g_ovf_cnt = 0;
    }
    if (i < N_NODES) g_degi[i] = 0;
}

__device__ __forceinline__ void load_edge(const void* ei_raw, bool is64,
                                          int e, int& s, int& d) {
    if (is64) {
        const long long* ei = (const long long*)ei_raw;
        s = (int)ei[e];
        d = (int)ei[NE + e];
    } else {
        const int* ei = (const int*)ei_raw;
        s = ei[e];
        d = ei[NE + e];
    }
}

// ---------------------------------------------------------------------------
// fill: single pass builds slot adjacency AND degrees. All 16 atomicAdds are
// issued before any dependent store (MLP ~16). Rare deg>SLOTS entries go to
// a small overflow list (correct for any degree).
// ---------------------------------------------------------------------------
__global__ void __launch_bounds__(256, 4)
fill_kernel(const void* __restrict__ ei_raw) {
    bool is64 = (g_is64 != 0);
    int base  = blockIdx.x * 2048 + threadIdx.x;

    int s[8], d[8];
    bool ok[8];
#pragma unroll
    for (int j = 0; j < 8; j++) {
        int e = base + j * 256;
        ok[j] = (e < NE);
        if (ok[j]) load_edge(ei_raw, is64, e, s[j], d[j]);
    }

    int p[8], q[8];
#pragma unroll
    for (int j = 0; j < 8; j++)
        if (ok[j]) p[j] = atomicAdd(&g_degi[s[j]], 1);
#pragma unroll
    for (int j = 0; j < 8; j++)
        if (ok[j]) q[j] = atomicAdd(&g_degi[d[j]], 1);

#pragma unroll
    for (int j = 0; j < 8; j++) {
        if (ok[j]) {
            if (p[j] < SLOTS) {
                g_adj[(size_t)s[j] * SLOTS + p[j]] = d[j];
            } else {
                int o = atomicAdd(&g_ovf_cnt, 1);
                g_ovf_node[o] = s[j];
                g_ovf_nbr[o]  = d[j];
            }
            if (q[j] < SLOTS) {
                g_adj[(size_t)d[j] * SLOTS + q[j]] = s[j];
            } else {
                int o = atomicAdd(&g_ovf_cnt, 1);
                g_ovf_node[o] = d[j];
                g_ovf_nbr[o]  = s[j];
            }
        }
    }
}

// ---------------------------------------------------------------------------
// Persistent GEMM: Yh = half(X @ W), tf32 wmma, W staged once per block.
// ---------------------------------------------------------------------------
__device__ __forceinline__ void gemm_tile_body(int tile, const float* __restrict__ X,
                                               const float* w_sh, float* csh) {
    int tid  = threadIdx.x;
    int warp = tid >> 5;
    int lane = tid & 31;

    int row0 = tile * 128 + warp * 16;
    if (row0 >= N_NODES) return;

    wmma::fragment<wmma::accumulator, 16, 16, 8, float> c[8];
#pragma unroll
    for (int n = 0; n < 8; n++) wmma::fill_fragment(c[n], 0.0f);

    const float* a_base = X + (size_t)row0 * D;
#pragma unroll 1
    for (int kc = 0; kc < 16; kc++) {
        wmma::fragment<wmma::matrix_a, 16, 16, 8, wmma::precision::tf32, wmma::row_major> a;
        wmma::load_matrix_sync(a, a_base + kc * 8, D);
#pragma unroll
        for (int t = 0; t < a.num_elements; t++) a.x[t] = wmma::__float_to_tf32(a.x[t]);
#pragma unroll
        for (int n = 0; n < 8; n++) {
            wmma::fragment<wmma::matrix_b, 16, 16, 8, wmma::precision::tf32, wmma::row_major> b;
            wmma::load_matrix_sync(b, w_sh + (kc * 8) * D + n * 16, D);
#pragma unroll
            for (int t = 0; t < b.num_elements; t++) b.x[t] = wmma::__float_to_tf32(b.x[t]);
            wmma::mma_sync(c[n], a, b, c[n]);
        }
    }

    float* cstg = csh + warp * 16 * 64;
#pragma unroll
    for (int h = 0; h < 2; h++) {
#pragma unroll
        for (int n = 0; n < 4; n++)
            wmma::store_matrix_sync(cstg + n * 16, c[h * 4 + n], 64, wmma::mem_row_major);
        __syncwarp();
#pragma unroll
        for (int r = 0; r < 16; r++) {
            float2 v = ((const float2*)(cstg + r * 64))[lane];
            __half2 hp = __float22half2_rn(v);
            ((unsigned*)(g_Yh + (size_t)(row0 + r) * D + h * 64))[lane] = *(unsigned*)&hp;
        }
        __syncwarp();
    }
}

__global__ void __launch_bounds__(256)
gemm_kernel(const float* __restrict__ X, const float* __restrict__ W) {
    extern __shared__ float sh[];
    float* w_sh = sh;
    float* csh  = sh + SMEM_W_FLOATS;
    int tid = threadIdx.x;
    const float4* W4  = (const float4*)W;
    float4*       sh4 = (float4*)w_sh;
#pragma unroll
    for (int i = 0; i < 16; i++) sh4[tid + i * 256] = W4[tid + i * 256];
    __syncthreads();
#pragma unroll 1
    for (int tile = blockIdx.x; tile < GEMM_TILES; tile += GEMM_BLOCKS)
        gemm_tile_body(tile, X, w_sh, csh);
}

// ---------------------------------------------------------------------------
// Gather: out[i] = relu((Y[i] + sum_nbr Y[j]) / deg[i]).
// Slot rows are 128B-aligned -> each 32-index read is one L2 line.
// Rare deg>SLOTS warps additionally scan the tiny overflow list.
// ---------------------------------------------------------------------------
__device__ __forceinline__ void acc_half4(float4& acc, uint2 raw) {
    __half2 h01 = *(__half2*)&raw.x;
    __half2 h23 = *(__half2*)&raw.y;
    float2 f01 = __half22float2(h01);
    float2 f23 = __half22float2(h23);
    acc.x += f01.x; acc.y += f01.y; acc.z += f23.x; acc.w += f23.y;
}

__global__ void __launch_bounds__(256)
gather_kernel(float* __restrict__ out) {
    int w    = (blockIdx.x * blockDim.x + threadIdx.x) >> 5;
    int lane = threadIdx.x & 31;
    if (w >= N_NODES) return;

    const int* adjw = g_adj + (size_t)w * SLOTS;
    int degn  = g_degi[w];
    int dmain = min(degn, SLOTS);

    const uint2* Y2 = (const uint2*)g_Yh;
    float4 acc = make_float4(0.f, 0.f, 0.f, 0.f);
    acc_half4(acc, __ldg(Y2 + (size_t)w * 32 + lane));   // self term

    for (int t = 0; t < dmain; t += 32) {
        int cnt   = min(32, dmain - t);
        int myidx = (lane < cnt) ? adjw[t + lane] : 0;
#pragma unroll 8
        for (int k = 0; k < cnt; k++) {
            int u = __shfl_sync(0xffffffffu, myidx, k);
            acc_half4(acc, __ldg(Y2 + (size_t)u * 32 + lane));
        }
    }

    if (degn > SLOTS) {   // extremely rare: scan tiny overflow list
        int cnt = g_ovf_cnt;
        for (int i = 0; i < cnt; i++) {
            if (g_ovf_node[i] == w) {
                int u = g_ovf_nbr[i];
                acc_half4(acc, __ldg(Y2 + (size_t)u * 32 + lane));
            }
        }
    }

    float inv = 1.0f / (float)degn;
    float4 o;
    o.x = fmaxf(acc.x * inv, 0.0f);
    o.y = fmaxf(acc.y * inv, 0.0f);
    o.z = fmaxf(acc.z * inv, 0.0f);
    o.w = fmaxf(acc.w * inv, 0.0f);
    ((float4*)out)[(size_t)w * 32 + lane] = o;
}

// ---------------------------------------------------------------------------
// Launch: adjacency build forked onto a side stream, concurrent with the
// persistent GEMM. Join, then gather. (Launch boundaries are the only
// cross-phase synchronization — no in-kernel grid barriers.)
// ---------------------------------------------------------------------------
extern "C" void kernel_launch(void* const* d_in, const int* in_sizes, int n_in,
                              void* d_out, int out_size) {
    const float* X   = (const float*)d_in[0];
    const float* W   = (const float*)d_in[1];
    const void*  EI  = d_in[2];
    float*       out = (float*)d_out;

    cudaFuncSetAttribute(gemm_kernel,
                         cudaFuncAttributeMaxDynamicSharedMemorySize, SMEM_GEMM);

    cudaStream_t s2;
    cudaStreamCreateWithFlags(&s2, cudaStreamNonBlocking);
    cudaEvent_t evFork, evCsr;
    cudaEventCreateWithFlags(&evFork, cudaEventDisableTiming);
    cudaEventCreateWithFlags(&evCsr, cudaEventDisableTiming);

    // fork
    cudaEventRecord(evFork, 0);
    cudaStreamWaitEvent(s2, evFork, 0);

    // s2: adjacency build (latency/atomic-bound)
    probe_zero_kernel<<<NB, 256, 0, s2>>>((const int*)EI);
    fill_kernel<<<EDGE_BLOCKS8, 256, 0, s2>>>(EI);
    cudaEventRecord(evCsr, s2);

    // s0: persistent GEMM (tensor-bound), concurrent with adjacency build
    gemm_kernel<<<GEMM_BLOCKS, 256, SMEM_GEMM>>>(X, W);

    // join, then gather
    cudaStreamWaitEvent(0, evCsr, 0);
    gather_kernel<<<(N_NODES * 32 + 255) / 256, 256>>>(out);
}